// round 12
// baseline (speedup 1.0000x reference)
#include <cuda_runtime.h>

typedef unsigned long long ull;

#define THREADS 256
#define SPC     32            // samples per CTA
#define NBLK    256           // 8192 / 32
#define DT      0.1f
#define HDT     0.05f
#define LOG2PI  1.83787706640934548356f

// Interleaved weight matrix: WG[j][k] = (W2[j,k], H[j,k]) packed as f32x2,
// where H[j][k] = W2[j][k] * sum_i W1[i][j]*W3[k][i]  (divergence matrix).
__device__ ull g_WG[256 * 256];

// ---------------- packed f32x2 helpers ----------------
__device__ __forceinline__ ull pack2(float lo, float hi) {
    ull v;
    asm("mov.b64 %0, {%1,%2};" : "=l"(v)
        : "r"(__float_as_uint(lo)), "r"(__float_as_uint(hi)));
    return v;
}
__device__ __forceinline__ void unpack2(ull v, float& lo, float& hi) {
    unsigned a, b;
    asm("mov.b64 {%0,%1}, %2;" : "=r"(a), "=r"(b) : "l"(v));
    lo = __uint_as_float(a); hi = __uint_as_float(b);
}
__device__ __forceinline__ ull fma2(ull a, ull b, ull c) {
    ull d;
    asm("fma.rn.f32x2 %0, %1, %2, %3;" : "=l"(d) : "l"(a), "l"(b), "l"(c));
    return d;
}

// ---------------- shared-memory layout (float offsets) ----------------
#define OFF_W1T 0        // [j][0..15]=W1 z-rows, [16]=W1 t-row, [17]=b1; stride 20 -> 5120
#define OFF_B2  5120     // 256
#define OFF_W3D 5376     // w3 pairs [p][k] ull, row stride 258 ull (516 f) -> 4128 floats
#define OFF_B3  9504     // 16
#define OFF_Z   9520     // z_eval [s*17+i] -> 544
#define OFF_HD  10064    // (h1,d1) ull pairs [j*32 + swz(s)] (16384 f);
                         // ALIASED as h2dup [s][k] ull, row stride 258 ull -> 16512 f
#define OFF_WD  26576    // per-warp div partials [w*32+s] (256)
#define OFF_DV  26832    // div[s] (32)
#define SMEM_FLOATS 26864
#define SMEM_BYTES (SMEM_FLOATS * 4)

// hd-row 16B-chunk swizzle: chunk c (0..15) -> (c & ~3) | ((c & 3) ^ (c >> 2))
// Makes the 4 sq-segment loads bank-disjoint (verified per-q bank bases).

// ---------------- precompute interleaved WG ----------------
__global__ void comp_WG(const float* __restrict__ W1,
                        const float* __restrict__ W2,
                        const float* __restrict__ W3) {
    int j = blockIdx.x;      // 0..255
    int k = threadIdx.x;     // 0..255
    float g = 0.0f;
#pragma unroll
    for (int i = 0; i < 16; i++)
        g = fmaf(W1[i * 256 + j], W3[k * 16 + i], g);
    float w = W2[j * 256 + k];
    g_WG[j * 256 + k] = pack2(w, g * w);
}

// ---------------- main CNF kernel ----------------
__global__ __launch_bounds__(THREADS, 2)
void cnf_kernel(const float* __restrict__ x,
                const float* __restrict__ W1, const float* __restrict__ b1,
                const float* __restrict__ W2, const float* __restrict__ b2,
                const float* __restrict__ W3, const float* __restrict__ b3,
                float* __restrict__ out) {
    extern __shared__ float sm[];
    ull* hdp = (ull*)(sm + OFF_HD);
    const int tid  = threadIdx.x;
    const int lane = tid & 31;
    const int warp = tid >> 5;

    // ---- stage weights into shared ----
#pragma unroll
    for (int i = 0; i < 17; i++)
        sm[OFF_W1T + tid * 20 + i] = W1[i * 256 + tid];
    sm[OFF_W1T + tid * 20 + 17] = b1[tid];
    sm[OFF_B2 + tid] = b2[tid];
    {   // W3 as (2i,2i+1) pairs: w3d[p*258 + k], p = head-pair 0..7
        ull* w3d = (ull*)(sm + OFF_W3D);
        const int p = tid >> 5;
#pragma unroll
        for (int q = 0; q < 8; q++) {
            const int k = lane + (q << 5);
            w3d[p * 258 + k] = pack2(W3[k * 16 + 2 * p], W3[k * 16 + 2 * p + 1]);
        }
    }
    if (tid < 16) sm[OFF_B3 + tid] = b3[tid];

    // ---- RK4 state mapping (phases A/C2): thread t -> sample s=t>>3, comps (i0,i0+1) ----
    const int s  = tid >> 3;
    const int i0 = (tid & 7) << 1;
    const int gid = blockIdx.x * SPC + s;
    float z0a = x[gid * 16 + i0];
    float z0b = x[gid * 16 + i0 + 1];
    sm[OFF_Z + s * 17 + i0]     = z0a;
    sm[OFF_Z + s * 17 + i0 + 1] = z0b;
    float ka = 0.0f, kb = 0.0f;
    float divsum = 0.0f;

    // ---- phase-A hd-store swizzled slot for this lane's sample ----
    const int cA  = lane >> 1;
    const int cAp = (cA & ~3) | ((cA & 3) ^ (cA >> 2));
    const int su  = (cAp << 1) | (lane & 1);          // swizzled ull slot within row

    // ---- phase-B micro-tile mapping: warp -> 32-k block; lane = sq*8 + kq ----
    const int kq = lane & 7;          // k group of 4
    const int sq = lane >> 3;         // sample group of 8
    const int k0 = (warp << 5) + (kq << 2);
    const int s0 = sq << 3;           // first of 8 samples
    // swizzled hd chunk offsets (ull) for q = 0..3
    const int o0 = ((sq << 2) | (0 ^ sq)) << 1;
    const int o1 = ((sq << 2) | (1 ^ sq)) << 1;
    const int o2 = ((sq << 2) | (2 ^ sq)) << 1;
    const int o3 = ((sq << 2) | (3 ^ sq)) << 1;
    __syncthreads();

    for (int st = 0; st < 10; ++st) {
        const float tn = (float)st * DT;
#pragma unroll 1
        for (int sub = 0; sub < 4; ++sub) {
            const float te = tn + ((sub == 0) ? 0.0f : ((sub == 3) ? DT : HDT));

            // ======== Phase A: layer 1. warp -> j range, lane -> sample ========
            {
                float zr[16];
#pragma unroll
                for (int i = 0; i < 16; i++) zr[i] = sm[OFF_Z + lane * 17 + i];
                const int jbase = warp << 5;
#pragma unroll 4
                for (int jj = 0; jj < 32; jj++) {
                    const int j = jbase + jj;
                    const float* wr = sm + OFF_W1T + j * 20;
                    float4 w0 = *(const float4*)(wr);
                    float4 w1v = *(const float4*)(wr + 4);
                    float4 w2v = *(const float4*)(wr + 8);
                    float4 w3v = *(const float4*)(wr + 12);
                    float2 tb = *(const float2*)(wr + 16);
                    float a = fmaf(te, tb.x, tb.y);
                    a = fmaf(zr[0],  w0.x, a);  a = fmaf(zr[1],  w0.y, a);
                    a = fmaf(zr[2],  w0.z, a);  a = fmaf(zr[3],  w0.w, a);
                    a = fmaf(zr[4],  w1v.x, a); a = fmaf(zr[5],  w1v.y, a);
                    a = fmaf(zr[6],  w1v.z, a); a = fmaf(zr[7],  w1v.w, a);
                    a = fmaf(zr[8],  w2v.x, a); a = fmaf(zr[9],  w2v.y, a);
                    a = fmaf(zr[10], w2v.z, a); a = fmaf(zr[11], w2v.w, a);
                    a = fmaf(zr[12], w3v.x, a); a = fmaf(zr[13], w3v.y, a);
                    a = fmaf(zr[14], w3v.z, a); a = fmaf(zr[15], w3v.w, a);
                    float e  = __expf(-a);
                    float sg = __fdividef(1.0f, 1.0f + e);
                    float h  = a * sg;                      // silu
                    float d  = fmaf(h, 1.0f - sg, sg);      // silu'
                    hdp[(j << 5) + su] = pack2(h, d);       // swizzled (h,d)
                }
            }
            __syncthreads();

            // ======== Phase B: ONE fused f32x2 GEMM, weight prefetch 1-ahead ====
            // acc[sp*4+kk] lanes: lo = a2[s,k] (h1·W2), hi = u[s,k] (d1·H)
            ull acc[32];
            {
                const float4 b2v = *(const float4*)(sm + OFF_B2 + k0);
                const ull bi0 = pack2(b2v.x, 0.0f), bi1 = pack2(b2v.y, 0.0f);
                const ull bi2 = pack2(b2v.z, 0.0f), bi3 = pack2(b2v.w, 0.0f);
#pragma unroll
                for (int sp = 0; sp < 8; sp++) {
                    acc[sp * 4 + 0] = bi0; acc[sp * 4 + 1] = bi1;
                    acc[sp * 4 + 2] = bi2; acc[sp * 4 + 3] = bi3;
                }
                const ull* wgp = g_WG + k0;
                ulonglong2 wc0 = __ldg((const ulonglong2*)(wgp));
                ulonglong2 wc1 = __ldg((const ulonglong2*)(wgp + 2));
#pragma unroll 2
                for (int j = 0; j < 256; j++) {
                    const int jn = (j + 1) & 255;
                    ulonglong2 wn0 = __ldg((const ulonglong2*)(wgp + (jn << 8)));
                    ulonglong2 wn1 = __ldg((const ulonglong2*)(wgp + (jn << 8) + 2));
                    const ull* hr = hdp + (j << 5);
                    ulonglong2 hA = *(const ulonglong2*)(hr + o0);
                    ulonglong2 hB = *(const ulonglong2*)(hr + o1);
                    ulonglong2 hC = *(const ulonglong2*)(hr + o2);
                    ulonglong2 hD = *(const ulonglong2*)(hr + o3);
                    const ull hs[8] = {hA.x, hA.y, hB.x, hB.y,
                                       hC.x, hC.y, hD.x, hD.y};
#pragma unroll
                    for (int sp = 0; sp < 8; sp++) {
                        acc[sp * 4 + 0] = fma2(hs[sp], wc0.x, acc[sp * 4 + 0]);
                        acc[sp * 4 + 1] = fma2(hs[sp], wc0.y, acc[sp * 4 + 1]);
                        acc[sp * 4 + 2] = fma2(hs[sp], wc1.x, acc[sp * 4 + 2]);
                        acc[sp * 4 + 3] = fma2(hs[sp], wc1.y, acc[sp * 4 + 3]);
                    }
                    wc0 = wn0; wc1 = wn1;
                }
            }

            // ======== Phase C1: silu(a2), div partial dp = sum_k u*silu'(a2) ====
            // acc is rewritten as duplicate-packed h2: acc[sp*4+kk] = (h,h)
            {
                float dps[8];
#pragma unroll
                for (int sp = 0; sp < 8; sp++) {
                    dps[sp] = 0.0f;
#pragma unroll
                    for (int kk = 0; kk < 4; kk++) {
                        float a, uu;
                        unpack2(acc[sp * 4 + kk], a, uu);
                        float e = __expf(-a);
                        float g = __fdividef(1.0f, 1.0f + e);
                        float h = a * g;
                        float d2 = fmaf(h, 1.0f - g, g);
                        dps[sp] = fmaf(uu, d2, dps[sp]);
                        acc[sp * 4 + kk] = pack2(h, h);      // dup-packed h2
                    }
                }
                // reduce each sample's partial over the 8 kq lanes (lane bits 0..2)
#pragma unroll
                for (int sp = 0; sp < 8; sp++) {
                    dps[sp] += __shfl_xor_sync(0xffffffffu, dps[sp], 1);
                    dps[sp] += __shfl_xor_sync(0xffffffffu, dps[sp], 2);
                    dps[sp] += __shfl_xor_sync(0xffffffffu, dps[sp], 4);
                }
                if (kq == 0) {
#pragma unroll
                    for (int sp = 0; sp < 8; sp++)
                        sm[OFF_WD + warp * 32 + s0 + sp] = dps[sp];
                }
            }
            __syncthreads();   // phase-B readers of hd done; WD visible

            // ======== h2dup store ([s][258-ull rows]) + cross-warp div reduce ====
            {
                ull* h2w = (ull*)(sm + OFF_HD);
#pragma unroll
                for (int sp = 0; sp < 8; sp++) {
                    ull* r = h2w + (s0 + sp) * 258 + k0;
                    ulonglong2 v0, v1;
                    v0.x = acc[sp * 4 + 0]; v0.y = acc[sp * 4 + 1];
                    v1.x = acc[sp * 4 + 2]; v1.y = acc[sp * 4 + 3];
                    *(ulonglong2*)(r)     = v0;
                    *(ulonglong2*)(r + 2) = v1;
                }
                if (tid < 32) {
                    float dv = 0.0f;
#pragma unroll
                    for (int w = 0; w < 8; w++) dv += sm[OFF_WD + w * 32 + tid];
                    sm[OFF_DV + tid] = dv;
                }
            }
            __syncthreads();

            // ======== Phase C2: layer 3 (pure fma2 stream) + RK4 update =========
            {
                const ull* h2r = (const ull*)(sm + OFF_HD) + s * 258;
                const ull* w3r = (const ull*)(sm + OFF_W3D) + (tid & 7) * 258;
                ull f0a = pack2(sm[OFF_B3 + i0], sm[OFF_B3 + i0 + 1]);
                ull f1a = 0ULL, f2a = 0ULL, f3a = 0ULL;
#pragma unroll 4
                for (int k = 0; k < 256; k += 4) {
                    ulonglong2 hh0 = *(const ulonglong2*)(h2r + k);
                    ulonglong2 ww0 = *(const ulonglong2*)(w3r + k);
                    ulonglong2 hh1 = *(const ulonglong2*)(h2r + k + 2);
                    ulonglong2 ww1 = *(const ulonglong2*)(w3r + k + 2);
                    f0a = fma2(hh0.x, ww0.x, f0a);
                    f1a = fma2(hh0.y, ww0.y, f1a);
                    f2a = fma2(hh1.x, ww1.x, f2a);
                    f3a = fma2(hh1.y, ww1.y, f3a);
                }
                float p0, p1, q0, q1, r0, r1, t0, t1;
                unpack2(f0a, p0, p1); unpack2(f1a, q0, q1);
                unpack2(f2a, r0, r1); unpack2(f3a, t0, t1);
                float f0 = (p0 + q0) + (r0 + t0);
                float f1 = (p1 + q1) + (r1 + t1);
                const float wgt = (sub == 1 || sub == 2) ? 2.0f : 1.0f;
                ka = fmaf(wgt, f0, ka);
                kb = fmaf(wgt, f1, kb);
                if ((tid & 7) == 0) divsum = fmaf(wgt, sm[OFF_DV + s], divsum);
                if (sub < 3) {
                    const float c = (sub == 2) ? DT : HDT;
                    sm[OFF_Z + s * 17 + i0]     = fmaf(c, f0, z0a);
                    sm[OFF_Z + s * 17 + i0 + 1] = fmaf(c, f1, z0b);
                } else {
                    z0a = fmaf(DT / 6.0f, ka, z0a);
                    z0b = fmaf(DT / 6.0f, kb, z0b);
                    ka = 0.0f; kb = 0.0f;
                    sm[OFF_Z + s * 17 + i0]     = z0a;
                    sm[OFF_Z + s * 17 + i0 + 1] = z0b;
                }
            }
            __syncthreads();
        }
    }

    // ---- final: logpz - logp1 ----
    float ss = z0a * z0a + z0b * z0b;
    ss += __shfl_xor_sync(0xffffffffu, ss, 1);
    ss += __shfl_xor_sync(0xffffffffu, ss, 2);
    ss += __shfl_xor_sync(0xffffffffu, ss, 4);
    if ((tid & 7) == 0)
        out[gid] = -0.5f * (ss + 16.0f * LOG2PI) + (DT / 6.0f) * divsum;
}

extern "C" void kernel_launch(void* const* d_in, const int* in_sizes, int n_in,
                              void* d_out, int out_size) {
    const float* x  = (const float*)d_in[0];
    const float* W1 = (const float*)d_in[1];
    const float* b1 = (const float*)d_in[2];
    const float* W2 = (const float*)d_in[3];
    const float* b2 = (const float*)d_in[4];
    const float* W3 = (const float*)d_in[5];
    const float* b3 = (const float*)d_in[6];
    float* out = (float*)d_out;

    comp_WG<<<256, 256>>>(W1, W2, W3);

    cudaFuncSetAttribute(cnf_kernel, cudaFuncAttributeMaxDynamicSharedMemorySize,
                         SMEM_BYTES);
    cnf_kernel<<<NBLK, THREADS, SMEM_BYTES>>>(x, W1, b1, W2, b2, W3, b3, out);
}

// round 14
// speedup vs baseline: 2.7260x; 2.7260x over previous
#include <cuda_runtime.h>
#include <cuda_bf16.h>

typedef unsigned long long ull;
typedef unsigned int u32;

#define THREADS 256
#define SPC     32
#define NBLK    256
#define DT      0.1f
#define HDT     0.05f
#define LOG2PI  1.83787706640934548356f

// ---- SMEM byte offsets ----
#define A_HHI 0
#define A_HLO 16384
#define A_DHI 32768
#define A_DLO 49152
// h2dup aliases bytes [0, 66048) after MMAs complete: ull[s*258 + k]
#define W1TB  66048
#define W3DB  86528
// ---- SMEM float indices ----
#define W1Tf  16512     // [j][20]: 16 W1 z-rows, W1 t-row, b1
#define B2f   25760
#define B3f   26016
#define Zf    26032     // z_eval [s*20 + i]
#define WDf   26672     // per-warp div partials [w*32 + s]
#define SMEMSZ 107712

// B fragments in mma layout: [mat 0..3][kt 0..15][ntabs 0..31][lane 0..31] uint2
// mats: 0=W2hi 1=W2lo 2=Hhi 3=Hlo;  H[j][n] = W2[j][n]*sum_i W1[i][j]W3[n][i]
__device__ __align__(16) uint2 g_Bf[4 * 16 * 32 * 32];

// ---------------- helpers ----------------
__device__ __forceinline__ ull pack2(float lo, float hi) {
    ull v;
    asm("mov.b64 %0, {%1,%2};" : "=l"(v)
        : "r"(__float_as_uint(lo)), "r"(__float_as_uint(hi)));
    return v;
}
__device__ __forceinline__ void unpack2(ull v, float& lo, float& hi) {
    u32 a, b;
    asm("mov.b64 {%0,%1}, %2;" : "=r"(a), "=r"(b) : "l"(v));
    lo = __uint_as_float(a); hi = __uint_as_float(b);
}
__device__ __forceinline__ ull fma2(ull a, ull b, ull c) {
    ull d;
    asm("fma.rn.f32x2 %0, %1, %2, %3;" : "=l"(d) : "l"(a), "l"(b), "l"(c));
    return d;
}
__device__ __forceinline__ u32 bpack(float a, float b) {   // low16 <- a, high16 <- b
    u32 r;
    asm("cvt.rn.bf16x2.f32 %0, %1, %2;" : "=r"(r) : "f"(b), "f"(a));
    return r;
}
__device__ __forceinline__ float blo(u32 p) { return __uint_as_float(p << 16); }
__device__ __forceinline__ float bhi(u32 p) { return __uint_as_float(p & 0xFFFF0000u); }

// D += A(16x16) * B(16x8), bf16 in, f32 accum
__device__ __forceinline__ void mma16816(float* c, uint4 a, uint2 b) {
    asm("mma.sync.aligned.m16n8k16.row.col.f32.bf16.bf16.f32 "
        "{%0,%1,%2,%3}, {%4,%5,%6,%7}, {%8,%9}, {%0,%1,%2,%3};"
        : "+f"(c[0]), "+f"(c[1]), "+f"(c[2]), "+f"(c[3])
        : "r"(a.x), "r"(a.y), "r"(a.z), "r"(a.w), "r"(b.x), "r"(b.y));
}

__device__ __forceinline__ float l1a(const float* sm, int j, float te, const float* zr) {
    const float* wr = sm + W1Tf + j * 20;
    float4 w0 = *(const float4*)(wr);
    float4 w1v = *(const float4*)(wr + 4);
    float4 w2v = *(const float4*)(wr + 8);
    float4 w3v = *(const float4*)(wr + 12);
    float2 tb = *(const float2*)(wr + 16);
    float a = fmaf(te, tb.x, tb.y);
    a = fmaf(zr[0],  w0.x, a);  a = fmaf(zr[1],  w0.y, a);
    a = fmaf(zr[2],  w0.z, a);  a = fmaf(zr[3],  w0.w, a);
    a = fmaf(zr[4],  w1v.x, a); a = fmaf(zr[5],  w1v.y, a);
    a = fmaf(zr[6],  w1v.z, a); a = fmaf(zr[7],  w1v.w, a);
    a = fmaf(zr[8],  w2v.x, a); a = fmaf(zr[9],  w2v.y, a);
    a = fmaf(zr[10], w2v.z, a); a = fmaf(zr[11], w2v.w, a);
    a = fmaf(zr[12], w3v.x, a); a = fmaf(zr[13], w3v.y, a);
    a = fmaf(zr[14], w3v.z, a); a = fmaf(zr[15], w3v.w, a);
    return a;
}
__device__ __forceinline__ void silud(float a, float& h, float& d) {
    float e = __expf(-a);
    float g = __fdividef(1.0f, 1.0f + e);
    h = a * g;
    d = fmaf(h, 1.0f - g, g);
}

// ---------------- prep: B fragments in mma layout, bf16-split ----------------
__global__ void comp_Bf(const float* __restrict__ W1,
                        const float* __restrict__ W2,
                        const float* __restrict__ W3) {
    const int kt = blockIdx.x, ntabs = blockIdx.y;
    const int mat = threadIdx.x >> 5, lane = threadIdx.x & 31;
    const int g = lane >> 2, t = lane & 3;
    const int n = ntabs * 8 + g;
    float vv[4];
#pragma unroll
    for (int q = 0; q < 4; q++) {
        const int j = kt * 16 + t * 2 + (q & 1) + (q >> 1) * 8;
        float v = W2[j * 256 + n];
        if (mat >= 2) {
            float gg = 0.0f;
#pragma unroll
            for (int i = 0; i < 16; i++)
                gg = fmaf(W1[i * 256 + j], W3[n * 16 + i], gg);
            v *= gg;
        }
        if (mat & 1) {
            __nv_bfloat16 bh = __float2bfloat16(v);
            v = v - __bfloat162float(bh);
        }
        vv[q] = v;
    }
    g_Bf[((mat * 16 + kt) * 32 + ntabs) * 32 + lane] =
        make_uint2(bpack(vv[0], vv[1]), bpack(vv[2], vv[3]));
}

// ---------------- main CNF kernel (mma.sync bf16-split) ----------------
__global__ __launch_bounds__(THREADS, 2)
void cnf_mma(const float* __restrict__ x,
             const float* __restrict__ W1, const float* __restrict__ b1,
             const float* __restrict__ b2, const float* __restrict__ W3,
             const float* __restrict__ b3, float* __restrict__ out) {
    extern __shared__ float sm[];
    char* smc = (char*)sm;
    const int tid  = threadIdx.x;
    const int lane = tid & 31;
    const int warp = tid >> 5;
    const int g = lane >> 2;
    const int t = lane & 3;

    // ---- stage constants ----
#pragma unroll
    for (int i = 0; i < 17; i++)
        sm[W1Tf + tid * 20 + i] = W1[i * 256 + tid];
    sm[W1Tf + tid * 20 + 17] = b1[tid];
    sm[B2f + tid] = b2[tid];
    if (tid < 16) sm[B3f + tid] = b3[tid];
    {   // w3d[p][k] = (W3[k][2p], W3[k][2p+1]), row stride 258 ull
        ull* w3d = (ull*)(smc + W3DB);
        const int p = tid >> 5;
#pragma unroll
        for (int q = 0; q < 8; q++) {
            const int k = lane + (q << 5);
            w3d[p * 258 + k] = pack2(W3[k * 16 + 2 * p], W3[k * 16 + 2 * p + 1]);
        }
    }

    // ---- RK4 state: thread -> sample s=tid>>3, comps (i0, i0+1) ----
    const int s  = tid >> 3;
    const int i0 = (tid & 7) << 1;
    const int gid = blockIdx.x * SPC + s;
    float z0a = x[gid * 16 + i0];
    float z0b = x[gid * 16 + i0 + 1];
    sm[Zf + s * 20 + i0]     = z0a;
    sm[Zf + s * 20 + i0 + 1] = z0b;
    float ka = 0.0f, kb = 0.0f, divsum = 0.0f;
    __syncthreads();

    for (int st = 0; st < 10; ++st) {
        const float tn = (float)st * DT;
#pragma unroll 1
        for (int sub = 0; sub < 4; ++sub) {
            const float te = tn + ((sub == 0) ? 0.0f : ((sub == 3) ? DT : HDT));

            // ======== Phase A: layer 1 -> bf16-split A fragments in SMEM ========
#pragma unroll 1
            for (int mt = 0; mt < 2; mt++) {
                const int s1 = mt * 16 + g;
                float zr1[16], zr2[16];
#pragma unroll
                for (int q = 0; q < 4; q++) {
                    float4 v1 = *(const float4*)(sm + Zf + s1 * 20 + q * 4);
                    float4 v2 = *(const float4*)(sm + Zf + (s1 + 8) * 20 + q * 4);
                    zr1[4 * q] = v1.x; zr1[4 * q + 1] = v1.y; zr1[4 * q + 2] = v1.z; zr1[4 * q + 3] = v1.w;
                    zr2[4 * q] = v2.x; zr2[4 * q + 1] = v2.y; zr2[4 * q + 2] = v2.z; zr2[4 * q + 3] = v2.w;
                }
#pragma unroll 1
                for (int ks = 0; ks < 2; ks++) {
                    const int kt = warp + ks * 8;
                    const int jb = kt * 16 + t * 2;
                    u32 rh[4], rl[4], rdh[4], rdl[4];
#pragma unroll
                    for (int q = 0; q < 2; q++) {
                        const int ja = jb + q * 8;
                        float a00 = l1a(sm, ja, te, zr1);
                        float a01 = l1a(sm, ja + 1, te, zr1);
                        float a10 = l1a(sm, ja, te, zr2);
                        float a11 = l1a(sm, ja + 1, te, zr2);
                        float h00, d00, h01, d01, h10, d10, h11, d11;
                        silud(a00, h00, d00); silud(a01, h01, d01);
                        silud(a10, h10, d10); silud(a11, h11, d11);
                        u32 ph0 = bpack(h00, h01), ph1 = bpack(h10, h11);
                        u32 pd0 = bpack(d00, d01), pd1 = bpack(d10, d11);
                        rh[q * 2] = ph0;  rh[q * 2 + 1] = ph1;
                        rdh[q * 2] = pd0; rdh[q * 2 + 1] = pd1;
                        rl[q * 2]      = bpack(h00 - blo(ph0), h01 - bhi(ph0));
                        rl[q * 2 + 1]  = bpack(h10 - blo(ph1), h11 - bhi(ph1));
                        rdl[q * 2]     = bpack(d00 - blo(pd0), d01 - bhi(pd0));
                        rdl[q * 2 + 1] = bpack(d10 - blo(pd1), d11 - bhi(pd1));
                    }
                    const int off = ((mt * 16 + kt) * 32 + lane) * 16;
                    *(uint4*)(smc + A_HHI + off) = make_uint4(rh[0], rh[1], rh[2], rh[3]);
                    *(uint4*)(smc + A_HLO + off) = make_uint4(rl[0], rl[1], rl[2], rl[3]);
                    *(uint4*)(smc + A_DHI + off) = make_uint4(rdh[0], rdh[1], rdh[2], rdh[3]);
                    *(uint4*)(smc + A_DLO + off) = make_uint4(rdl[0], rdl[1], rdl[2], rdl[3]);
                }
            }
            __syncthreads();

            // ======== MMA phase: warp w -> columns [32w, 32w+32), both GEMMs ====
            float accA[32], accU[32];
#pragma unroll
            for (int i = 0; i < 32; i++) { accA[i] = 0.0f; accU[i] = 0.0f; }
#pragma unroll 1
            for (int kt = 0; kt < 16; kt++) {
                const int ab = (kt * 32 + lane) * 16;
                uint4 Ah0 = *(const uint4*)(smc + A_HHI + ab);
                uint4 Ah1 = *(const uint4*)(smc + A_HHI + ab + 8192);
                uint4 Al0 = *(const uint4*)(smc + A_HLO + ab);
                uint4 Al1 = *(const uint4*)(smc + A_HLO + ab + 8192);
                uint4 Dh0 = *(const uint4*)(smc + A_DHI + ab);
                uint4 Dh1 = *(const uint4*)(smc + A_DHI + ab + 8192);
                uint4 Dl0 = *(const uint4*)(smc + A_DLO + ab);
                uint4 Dl1 = *(const uint4*)(smc + A_DLO + ab + 8192);
                const int bidx = (kt * 32 + warp * 4) * 32 + lane;
#pragma unroll
                for (int nt = 0; nt < 4; nt++) {
                    uint2 Bwh = __ldg(&g_Bf[bidx + nt * 32]);
                    uint2 Bwl = __ldg(&g_Bf[bidx + nt * 32 + 16384]);
                    uint2 Bhh = __ldg(&g_Bf[bidx + nt * 32 + 32768]);
                    uint2 Bhl = __ldg(&g_Bf[bidx + nt * 32 + 49152]);
                    float* c0 = accA + nt * 4;
                    float* c1 = accA + 16 + nt * 4;
                    mma16816(c0, Ah0, Bwh); mma16816(c1, Ah1, Bwh);
                    mma16816(c0, Al0, Bwh); mma16816(c1, Al1, Bwh);
                    mma16816(c0, Ah0, Bwl); mma16816(c1, Ah1, Bwl);
                    float* u0 = accU + nt * 4;
                    float* u1 = accU + 16 + nt * 4;
                    mma16816(u0, Dh0, Bhh); mma16816(u1, Dh1, Bhh);
                    mma16816(u0, Dl0, Bhh); mma16816(u1, Dl1, Bhh);
                    mma16816(u0, Dh0, Bhl); mma16816(u1, Dh1, Bhl);
                }
            }
            __syncthreads();   // all warps done reading A region -> alias as h2

            // ======== Epilogue: bias + silu + div-dot, h2dup stores ========
            {
                float dp4[4] = {0.0f, 0.0f, 0.0f, 0.0f};
                ull* h2p = (ull*)smc;
#pragma unroll
                for (int mt = 0; mt < 2; mt++) {
#pragma unroll
                    for (int nt = 0; nt < 4; nt++) {
                        const int k0 = warp * 32 + nt * 8 + t * 2;
                        const int s1 = mt * 16 + g;
                        const float* cA = accA + mt * 16 + nt * 4;
                        const float* cU = accU + mt * 16 + nt * 4;
                        const float b2a = sm[B2f + k0], b2b = sm[B2f + k0 + 1];
                        float h0, d0, h1, d1, h2v, d2, h3, d3;
                        silud(cA[0] + b2a, h0, d0);
                        silud(cA[1] + b2b, h1, d1);
                        silud(cA[2] + b2a, h2v, d2);
                        silud(cA[3] + b2b, h3, d3);
                        dp4[mt * 2]     = fmaf(cU[0], d0, dp4[mt * 2]);
                        dp4[mt * 2]     = fmaf(cU[1], d1, dp4[mt * 2]);
                        dp4[mt * 2 + 1] = fmaf(cU[2], d2, dp4[mt * 2 + 1]);
                        dp4[mt * 2 + 1] = fmaf(cU[3], d3, dp4[mt * 2 + 1]);
                        ulonglong2 v0, v1;
                        v0.x = pack2(h0, h0);  v0.y = pack2(h1, h1);
                        v1.x = pack2(h2v, h2v); v1.y = pack2(h3, h3);
                        *(ulonglong2*)(h2p + s1 * 258 + k0)       = v0;
                        *(ulonglong2*)(h2p + (s1 + 8) * 258 + k0) = v1;
                    }
                }
#pragma unroll
                for (int i = 0; i < 4; i++) {
                    dp4[i] += __shfl_xor_sync(0xffffffffu, dp4[i], 1);
                    dp4[i] += __shfl_xor_sync(0xffffffffu, dp4[i], 2);
                }
                if (t == 0) {
                    sm[WDf + warp * 32 + g]      = dp4[0];
                    sm[WDf + warp * 32 + g + 8]  = dp4[1];
                    sm[WDf + warp * 32 + g + 16] = dp4[2];
                    sm[WDf + warp * 32 + g + 24] = dp4[3];
                }
            }
            __syncthreads();

            // ======== C2: layer 3 (pure fma2) + RK4 update ========
            {
                const ull* h2r = (const ull*)smc + s * 258;
                const ull* w3r = (const ull*)(smc + W3DB) + (tid & 7) * 258;
                ull f0a = pack2(sm[B3f + i0], sm[B3f + i0 + 1]);
                ull f1a = 0ULL, f2a = 0ULL, f3a = 0ULL;
#pragma unroll 4
                for (int k = 0; k < 256; k += 4) {
                    ulonglong2 hh0 = *(const ulonglong2*)(h2r + k);
                    ulonglong2 ww0 = *(const ulonglong2*)(w3r + k);
                    ulonglong2 hh1 = *(const ulonglong2*)(h2r + k + 2);
                    ulonglong2 ww1 = *(const ulonglong2*)(w3r + k + 2);
                    f0a = fma2(hh0.x, ww0.x, f0a);
                    f1a = fma2(hh0.y, ww0.y, f1a);
                    f2a = fma2(hh1.x, ww1.x, f2a);
                    f3a = fma2(hh1.y, ww1.y, f3a);
                }
                float p0, p1, q0, q1, r0, r1, t0, t1;
                unpack2(f0a, p0, p1); unpack2(f1a, q0, q1);
                unpack2(f2a, r0, r1); unpack2(f3a, t0, t1);
                const float f0 = (p0 + q0) + (r0 + t0);
                const float f1 = (p1 + q1) + (r1 + t1);
                const float wgt = (sub == 1 || sub == 2) ? 2.0f : 1.0f;
                ka = fmaf(wgt, f0, ka);
                kb = fmaf(wgt, f1, kb);
                if ((tid & 7) == 0) {
                    float dv = 0.0f;
#pragma unroll
                    for (int w = 0; w < 8; w++) dv += sm[WDf + w * 32 + s];
                    divsum = fmaf(wgt, dv, divsum);
                }
                if (sub < 3) {
                    const float c = (sub == 2) ? DT : HDT;
                    sm[Zf + s * 20 + i0]     = fmaf(c, f0, z0a);
                    sm[Zf + s * 20 + i0 + 1] = fmaf(c, f1, z0b);
                } else {
                    z0a = fmaf(DT / 6.0f, ka, z0a);
                    z0b = fmaf(DT / 6.0f, kb, z0b);
                    ka = 0.0f; kb = 0.0f;
                    sm[Zf + s * 20 + i0]     = z0a;
                    sm[Zf + s * 20 + i0 + 1] = z0b;
                }
            }
            __syncthreads();
        }
    }

    // ---- final: logpz - logp1 ----
    float ss = z0a * z0a + z0b * z0b;
    ss += __shfl_xor_sync(0xffffffffu, ss, 1);
    ss += __shfl_xor_sync(0xffffffffu, ss, 2);
    ss += __shfl_xor_sync(0xffffffffu, ss, 4);
    if ((tid & 7) == 0)
        out[gid] = -0.5f * (ss + 16.0f * LOG2PI) + (DT / 6.0f) * divsum;
}

extern "C" void kernel_launch(void* const* d_in, const int* in_sizes, int n_in,
                              void* d_out, int out_size) {
    const float* x  = (const float*)d_in[0];
    const float* W1 = (const float*)d_in[1];
    const float* b1 = (const float*)d_in[2];
    const float* W2 = (const float*)d_in[3];
    const float* b2 = (const float*)d_in[4];
    const float* W3 = (const float*)d_in[5];
    const float* b3 = (const float*)d_in[6];
    float* out = (float*)d_out;

    comp_Bf<<<dim3(16, 32), 128>>>(W1, W2, W3);

    cudaFuncSetAttribute(cnf_mma, cudaFuncAttributeMaxDynamicSharedMemorySize, SMEMSZ);
    cnf_mma<<<NBLK, THREADS, SMEMSZ>>>(x, W1, b1, b2, W3, b3, out);
}

// round 16
// speedup vs baseline: 3.4477x; 1.2648x over previous
#include <cuda_runtime.h>
#include <cuda_bf16.h>

typedef unsigned long long ull;
typedef unsigned int u32;

#define THREADS 256
#define SPC     32
#define NBLK    256
#define DT      0.1f
#define HDT     0.05f
#define LOG2PI  1.83787706640934548356f

// ---- SMEM byte offsets ----
#define A_HHI 0
#define A_HLO 16384
#define A_DHI 32768
#define A_DLO 49152
// layer-3 partial-D region aliases A tiles. SAFE ONLY AFTER the barrier that
// follows the kt8..15 MMA loop (all MMA A-reads complete by then):
//   warp w<4 -> bytes [w*2048, w*2048+2048) inside A_HHI
//   warp w>=4 -> bytes [16384+(w-4)*2048, ...) inside A_HLO
#define W1TB  65536
#define W3FB  86016    // W3 frags: uint2 [ktG*4 + nw*2 + sp][lane], 2048 entries, 16 KB
// ---- SMEM float indices ----
#define W1Tf  16384    // [j][20]: 16 W1 z-rows, W1 t-row, b1
#define B2f   25600
#define B3f   25856
#define Zf    25872    // z_eval [s*20 + i]
#define WDf   26512    // per-warp div partials [w*32 + s]
#define SMEMSZ 107072

// B fragments in mma layout: [mat 0..3][kt 0..15][ntabs 0..31][lane 0..31] uint2
// mats: 0=W2hi 1=W2lo 2=Hhi 3=Hlo;  H[j][n] = W2[j][n]*sum_i W1[i][j]W3[n][i]
__device__ __align__(16) uint2 g_Bf[4 * 16 * 32 * 32];

// ---------------- helpers ----------------
__device__ __forceinline__ u32 bpack(float a, float b) {   // low16 <- a, high16 <- b
    u32 r;
    asm("cvt.rn.bf16x2.f32 %0, %1, %2;" : "=r"(r) : "f"(b), "f"(a));
    return r;
}
__device__ __forceinline__ float blo(u32 p) { return __uint_as_float(p << 16); }
__device__ __forceinline__ float bhi(u32 p) { return __uint_as_float(p & 0xFFFF0000u); }

// D += A(16x16) * B(16x8), bf16 in, f32 accum
__device__ __forceinline__ void mma16816(float* c, uint4 a, uint2 b) {
    asm("mma.sync.aligned.m16n8k16.row.col.f32.bf16.bf16.f32 "
        "{%0,%1,%2,%3}, {%4,%5,%6,%7}, {%8,%9}, {%0,%1,%2,%3};"
        : "+f"(c[0]), "+f"(c[1]), "+f"(c[2]), "+f"(c[3])
        : "r"(a.x), "r"(a.y), "r"(a.z), "r"(a.w), "r"(b.x), "r"(b.y));
}

__device__ __forceinline__ float l1a(const float* sm, int j, float te, const float* zr) {
    const float* wr = sm + W1Tf + j * 20;
    float4 w0 = *(const float4*)(wr);
    float4 w1v = *(const float4*)(wr + 4);
    float4 w2v = *(const float4*)(wr + 8);
    float4 w3v = *(const float4*)(wr + 12);
    float2 tb = *(const float2*)(wr + 16);
    float a = fmaf(te, tb.x, tb.y);
    a = fmaf(zr[0],  w0.x, a);  a = fmaf(zr[1],  w0.y, a);
    a = fmaf(zr[2],  w0.z, a);  a = fmaf(zr[3],  w0.w, a);
    a = fmaf(zr[4],  w1v.x, a); a = fmaf(zr[5],  w1v.y, a);
    a = fmaf(zr[6],  w1v.z, a); a = fmaf(zr[7],  w1v.w, a);
    a = fmaf(zr[8],  w2v.x, a); a = fmaf(zr[9],  w2v.y, a);
    a = fmaf(zr[10], w2v.z, a); a = fmaf(zr[11], w2v.w, a);
    a = fmaf(zr[12], w3v.x, a); a = fmaf(zr[13], w3v.y, a);
    a = fmaf(zr[14], w3v.z, a); a = fmaf(zr[15], w3v.w, a);
    return a;
}
__device__ __forceinline__ void silud(float a, float& h, float& d) {
    float e = __expf(-a);
    float g = __fdividef(1.0f, 1.0f + e);
    h = a * g;
    d = fmaf(h, 1.0f - g, g);
}

// ---------------- prep: B fragments in mma layout, bf16-split ----------------
__global__ void comp_Bf(const float* __restrict__ W1,
                        const float* __restrict__ W2,
                        const float* __restrict__ W3) {
    const int kt = blockIdx.x, ntabs = blockIdx.y;
    const int mat = threadIdx.x >> 5, lane = threadIdx.x & 31;
    const int g = lane >> 2, t = lane & 3;
    const int n = ntabs * 8 + g;
    float vv[4];
#pragma unroll
    for (int q = 0; q < 4; q++) {
        const int j = kt * 16 + t * 2 + (q & 1) + (q >> 1) * 8;
        float v = W2[j * 256 + n];
        if (mat >= 2) {
            float gg = 0.0f;
#pragma unroll
            for (int i = 0; i < 16; i++)
                gg = fmaf(W1[i * 256 + j], W3[n * 16 + i], gg);
            v *= gg;
        }
        if (mat & 1) {
            __nv_bfloat16 bh = __float2bfloat16(v);
            v = v - __bfloat162float(bh);
        }
        vv[q] = v;
    }
    g_Bf[((mat * 16 + kt) * 32 + ntabs) * 32 + lane] =
        make_uint2(bpack(vv[0], vv[1]), bpack(vv[2], vv[3]));
}

// ---------------- main CNF kernel ----------------
__global__ __launch_bounds__(THREADS, 2)
void cnf_mma(const float* __restrict__ x,
             const float* __restrict__ W1, const float* __restrict__ b1,
             const float* __restrict__ b2, const float* __restrict__ W3,
             const float* __restrict__ b3, float* __restrict__ out) {
    extern __shared__ float sm[];
    char* smc = (char*)sm;
    const int tid  = threadIdx.x;
    const int lane = tid & 31;
    const int warp = tid >> 5;
    const int g = lane >> 2;
    const int t = lane & 3;

    // ---- stage constants ----
#pragma unroll
    for (int i = 0; i < 17; i++)
        sm[W1Tf + tid * 20 + i] = W1[i * 256 + tid];
    sm[W1Tf + tid * 20 + 17] = b1[tid];
    sm[B2f + tid] = b2[tid];
    if (tid < 16) sm[B3f + tid] = b3[tid];
    {   // W3 frags (hi/lo split): entry e -> [ktG][nw][sp][lane]
        uint2* w3f = (uint2*)(smc + W3FB);
#pragma unroll
        for (int q = 0; q < 8; q++) {
            const int e = tid + q * 256;
            const int el = e & 31, rest = e >> 5;
            const int sp = rest & 1, nw = (rest >> 1) & 1, ktG = rest >> 2;
            const int eg = el >> 2, et = el & 3;
            const int k0 = ktG * 16 + 2 * et;
            const int n = nw * 8 + eg;
            float v00 = W3[k0 * 16 + n],       v01 = W3[(k0 + 1) * 16 + n];
            float v10 = W3[(k0 + 8) * 16 + n], v11 = W3[(k0 + 9) * 16 + n];
            if (sp) {
                v00 -= __bfloat162float(__float2bfloat16(v00));
                v01 -= __bfloat162float(__float2bfloat16(v01));
                v10 -= __bfloat162float(__float2bfloat16(v10));
                v11 -= __bfloat162float(__float2bfloat16(v11));
            }
            w3f[e] = make_uint2(bpack(v00, v01), bpack(v10, v11));
        }
    }

    // ---- RK4 state: thread -> sample s=tid>>3, comps (i0, i0+1) ----
    const int s  = tid >> 3;
    const int i0 = (tid & 7) << 1;
    const int gid = blockIdx.x * SPC + s;
    float z0a = x[gid * 16 + i0];
    float z0b = x[gid * 16 + i0 + 1];
    sm[Zf + s * 20 + i0]     = z0a;
    sm[Zf + s * 20 + i0 + 1] = z0b;
    float ka = 0.0f, kb = 0.0f, divsum = 0.0f;
    // layer-3 partial base (floats): aliases A tiles; only touched post-barrier
    const int fpW = (warp < 4) ? (warp * 512) : (4096 + (warp - 4) * 512);
    __syncthreads();

    for (int st = 0; st < 10; ++st) {
        const float tn = (float)st * DT;
#pragma unroll 1
        for (int sub = 0; sub < 4; ++sub) {
            const float te = tn + ((sub == 0) ? 0.0f : ((sub == 3) ? DT : HDT));

            // ======== Phase A part 1: kt = warp ========
#pragma unroll 1
            for (int mt = 0; mt < 2; mt++) {
                const int s1 = mt * 16 + g;
                float zr1[16], zr2[16];
#pragma unroll
                for (int q = 0; q < 4; q++) {
                    float4 v1 = *(const float4*)(sm + Zf + s1 * 20 + q * 4);
                    float4 v2 = *(const float4*)(sm + Zf + (s1 + 8) * 20 + q * 4);
                    zr1[4 * q] = v1.x; zr1[4 * q + 1] = v1.y; zr1[4 * q + 2] = v1.z; zr1[4 * q + 3] = v1.w;
                    zr2[4 * q] = v2.x; zr2[4 * q + 1] = v2.y; zr2[4 * q + 2] = v2.z; zr2[4 * q + 3] = v2.w;
                }
                const int kt = warp;
                const int jb = kt * 16 + t * 2;
                u32 rh[4], rl[4], rdh[4], rdl[4];
#pragma unroll
                for (int q = 0; q < 2; q++) {
                    const int ja = jb + q * 8;
                    float a00 = l1a(sm, ja, te, zr1);
                    float a01 = l1a(sm, ja + 1, te, zr1);
                    float a10 = l1a(sm, ja, te, zr2);
                    float a11 = l1a(sm, ja + 1, te, zr2);
                    float h00, d00, h01, d01, h10, d10, h11, d11;
                    silud(a00, h00, d00); silud(a01, h01, d01);
                    silud(a10, h10, d10); silud(a11, h11, d11);
                    u32 ph0 = bpack(h00, h01), ph1 = bpack(h10, h11);
                    u32 pd0 = bpack(d00, d01), pd1 = bpack(d10, d11);
                    rh[q * 2] = ph0;  rh[q * 2 + 1] = ph1;
                    rdh[q * 2] = pd0; rdh[q * 2 + 1] = pd1;
                    rl[q * 2]      = bpack(h00 - blo(ph0), h01 - bhi(ph0));
                    rl[q * 2 + 1]  = bpack(h10 - blo(ph1), h11 - bhi(ph1));
                    rdl[q * 2]     = bpack(d00 - blo(pd0), d01 - bhi(pd0));
                    rdl[q * 2 + 1] = bpack(d10 - blo(pd1), d11 - bhi(pd1));
                }
                const int off = ((mt * 16 + kt) * 32 + lane) * 16;
                *(uint4*)(smc + A_HHI + off) = make_uint4(rh[0], rh[1], rh[2], rh[3]);
                *(uint4*)(smc + A_HLO + off) = make_uint4(rl[0], rl[1], rl[2], rl[3]);
                *(uint4*)(smc + A_DHI + off) = make_uint4(rdh[0], rdh[1], rdh[2], rdh[3]);
                *(uint4*)(smc + A_DLO + off) = make_uint4(rdl[0], rdl[1], rdl[2], rdl[3]);
            }
            __syncthreads();

            float accA[32], accU[32];
#pragma unroll
            for (int i = 0; i < 32; i++) { accA[i] = 0.0f; accU[i] = 0.0f; }

            // ======== Phase A part 2 (kt = warp+8) — overlaps others' MMA ========
#pragma unroll 1
            for (int mt = 0; mt < 2; mt++) {
                const int s1 = mt * 16 + g;
                float zr1[16], zr2[16];
#pragma unroll
                for (int q = 0; q < 4; q++) {
                    float4 v1 = *(const float4*)(sm + Zf + s1 * 20 + q * 4);
                    float4 v2 = *(const float4*)(sm + Zf + (s1 + 8) * 20 + q * 4);
                    zr1[4 * q] = v1.x; zr1[4 * q + 1] = v1.y; zr1[4 * q + 2] = v1.z; zr1[4 * q + 3] = v1.w;
                    zr2[4 * q] = v2.x; zr2[4 * q + 1] = v2.y; zr2[4 * q + 2] = v2.z; zr2[4 * q + 3] = v2.w;
                }
                const int kt = warp + 8;
                const int jb = kt * 16 + t * 2;
                u32 rh[4], rl[4], rdh[4], rdl[4];
#pragma unroll
                for (int q = 0; q < 2; q++) {
                    const int ja = jb + q * 8;
                    float a00 = l1a(sm, ja, te, zr1);
                    float a01 = l1a(sm, ja + 1, te, zr1);
                    float a10 = l1a(sm, ja, te, zr2);
                    float a11 = l1a(sm, ja + 1, te, zr2);
                    float h00, d00, h01, d01, h10, d10, h11, d11;
                    silud(a00, h00, d00); silud(a01, h01, d01);
                    silud(a10, h10, d10); silud(a11, h11, d11);
                    u32 ph0 = bpack(h00, h01), ph1 = bpack(h10, h11);
                    u32 pd0 = bpack(d00, d01), pd1 = bpack(d10, d11);
                    rh[q * 2] = ph0;  rh[q * 2 + 1] = ph1;
                    rdh[q * 2] = pd0; rdh[q * 2 + 1] = pd1;
                    rl[q * 2]      = bpack(h00 - blo(ph0), h01 - bhi(ph0));
                    rl[q * 2 + 1]  = bpack(h10 - blo(ph1), h11 - bhi(ph1));
                    rdl[q * 2]     = bpack(d00 - blo(pd0), d01 - bhi(pd0));
                    rdl[q * 2 + 1] = bpack(d10 - blo(pd1), d11 - bhi(pd1));
                }
                const int off = ((mt * 16 + kt) * 32 + lane) * 16;
                *(uint4*)(smc + A_HHI + off) = make_uint4(rh[0], rh[1], rh[2], rh[3]);
                *(uint4*)(smc + A_HLO + off) = make_uint4(rl[0], rl[1], rl[2], rl[3]);
                *(uint4*)(smc + A_DHI + off) = make_uint4(rdh[0], rdh[1], rdh[2], rdh[3]);
                *(uint4*)(smc + A_DLO + off) = make_uint4(rdl[0], rdl[1], rdl[2], rdl[3]);
            }

            // ======== MMA over kt 0..7 (A written before bar) ========
#pragma unroll 1
            for (int kt = 0; kt < 8; kt++) {
                const int ab = (kt * 32 + lane) * 16;
                uint4 Ah0 = *(const uint4*)(smc + A_HHI + ab);
                uint4 Ah1 = *(const uint4*)(smc + A_HHI + ab + 8192);
                uint4 Al0 = *(const uint4*)(smc + A_HLO + ab);
                uint4 Al1 = *(const uint4*)(smc + A_HLO + ab + 8192);
                uint4 Dh0 = *(const uint4*)(smc + A_DHI + ab);
                uint4 Dh1 = *(const uint4*)(smc + A_DHI + ab + 8192);
                uint4 Dl0 = *(const uint4*)(smc + A_DLO + ab);
                uint4 Dl1 = *(const uint4*)(smc + A_DLO + ab + 8192);
                const int bidx = (kt * 32 + warp * 4) * 32 + lane;
#pragma unroll
                for (int nt = 0; nt < 4; nt++) {
                    uint2 Bwh = __ldg(&g_Bf[bidx + nt * 32]);
                    uint2 Bwl = __ldg(&g_Bf[bidx + nt * 32 + 16384]);
                    uint2 Bhh = __ldg(&g_Bf[bidx + nt * 32 + 32768]);
                    uint2 Bhl = __ldg(&g_Bf[bidx + nt * 32 + 49152]);
                    float* c0 = accA + nt * 4;
                    float* c1 = accA + 16 + nt * 4;
                    mma16816(c0, Ah0, Bwh); mma16816(c1, Ah1, Bwh);
                    mma16816(c0, Al0, Bwh); mma16816(c1, Al1, Bwh);
                    mma16816(c0, Ah0, Bwl); mma16816(c1, Ah1, Bwl);
                    float* u0 = accU + nt * 4;
                    float* u1 = accU + 16 + nt * 4;
                    mma16816(u0, Dh0, Bhh); mma16816(u1, Dh1, Bhh);
                    mma16816(u0, Dl0, Bhh); mma16816(u1, Dl1, Bhh);
                    mma16816(u0, Dh0, Bhl); mma16816(u1, Dh1, Bhl);
                }
            }
            __syncthreads();   // part-2 A tiles visible

            // ======== MMA over kt 8..15 ========
#pragma unroll 1
            for (int kt = 8; kt < 16; kt++) {
                const int ab = (kt * 32 + lane) * 16;
                uint4 Ah0 = *(const uint4*)(smc + A_HHI + ab);
                uint4 Ah1 = *(const uint4*)(smc + A_HHI + ab + 8192);
                uint4 Al0 = *(const uint4*)(smc + A_HLO + ab);
                uint4 Al1 = *(const uint4*)(smc + A_HLO + ab + 8192);
                uint4 Dh0 = *(const uint4*)(smc + A_DHI + ab);
                uint4 Dh1 = *(const uint4*)(smc + A_DHI + ab + 8192);
                uint4 Dl0 = *(const uint4*)(smc + A_DLO + ab);
                uint4 Dl1 = *(const uint4*)(smc + A_DLO + ab + 8192);
                const int bidx = (kt * 32 + warp * 4) * 32 + lane;
#pragma unroll
                for (int nt = 0; nt < 4; nt++) {
                    uint2 Bwh = __ldg(&g_Bf[bidx + nt * 32]);
                    uint2 Bwl = __ldg(&g_Bf[bidx + nt * 32 + 16384]);
                    uint2 Bhh = __ldg(&g_Bf[bidx + nt * 32 + 32768]);
                    uint2 Bhl = __ldg(&g_Bf[bidx + nt * 32 + 49152]);
                    float* c0 = accA + nt * 4;
                    float* c1 = accA + 16 + nt * 4;
                    mma16816(c0, Ah0, Bwh); mma16816(c1, Ah1, Bwh);
                    mma16816(c0, Al0, Bwh); mma16816(c1, Al1, Bwh);
                    mma16816(c0, Ah0, Bwl); mma16816(c1, Ah1, Bwl);
                    float* u0 = accU + nt * 4;
                    float* u1 = accU + 16 + nt * 4;
                    mma16816(u0, Dh0, Bhh); mma16816(u1, Dh1, Bhh);
                    mma16816(u0, Dl0, Bhh); mma16816(u1, Dl1, Bhh);
                    mma16816(u0, Dh0, Bhl); mma16816(u1, Dh1, Bhl);
                }
            }
            // REQUIRED: all warps must finish reading A tiles before the
            // epilogue overwrites them with layer-3 partials (R15 NaN bug).
            __syncthreads();

            // ======== Epilogue: silu + div-dot + layer-3 mma on C frags ========
            {
                float dp4[4] = {0.0f, 0.0f, 0.0f, 0.0f};
                float D[16];
#pragma unroll
                for (int i = 0; i < 16; i++) D[i] = 0.0f;
                const uint2* w3f = (const uint2*)(smc + W3FB);
#pragma unroll
                for (int mt = 0; mt < 2; mt++) {
                    u32 fa[2][4], fl[2][4];
#pragma unroll
                    for (int nt = 0; nt < 4; nt++) {
                        const int k0 = warp * 32 + nt * 8 + t * 2;
                        const float* cA = accA + mt * 16 + nt * 4;
                        const float* cU = accU + mt * 16 + nt * 4;
                        const float b2a = sm[B2f + k0], b2b = sm[B2f + k0 + 1];
                        float h0, d0, h1, d1, h2v, d2, h3, d3;
                        silud(cA[0] + b2a, h0, d0);
                        silud(cA[1] + b2b, h1, d1);
                        silud(cA[2] + b2a, h2v, d2);
                        silud(cA[3] + b2b, h3, d3);
                        dp4[mt * 2]     = fmaf(cU[0], d0, dp4[mt * 2]);
                        dp4[mt * 2]     = fmaf(cU[1], d1, dp4[mt * 2]);
                        dp4[mt * 2 + 1] = fmaf(cU[2], d2, dp4[mt * 2 + 1]);
                        dp4[mt * 2 + 1] = fmaf(cU[3], d3, dp4[mt * 2 + 1]);
                        const int kti = nt >> 1, hf = (nt & 1) * 2;
                        u32 pA = bpack(h0, h1), pB = bpack(h2v, h3);
                        fa[kti][hf]     = pA;
                        fa[kti][hf + 1] = pB;
                        fl[kti][hf]     = bpack(h0 - blo(pA), h1 - bhi(pA));
                        fl[kti][hf + 1] = bpack(h2v - blo(pB), h3 - bhi(pB));
                    }
                    // layer-3: D[mt] += sum_kti h2frag x W3frag (3-term split)
#pragma unroll
                    for (int kti = 0; kti < 2; kti++) {
                        uint4 Ahi = make_uint4(fa[kti][0], fa[kti][1], fa[kti][2], fa[kti][3]);
                        uint4 Alo = make_uint4(fl[kti][0], fl[kti][1], fl[kti][2], fl[kti][3]);
                        const int ktG = warp * 2 + kti;
#pragma unroll
                        for (int nw = 0; nw < 2; nw++) {
                            uint2 Bh = w3f[(ktG * 4 + nw * 2 + 0) * 32 + lane];
                            uint2 Bl = w3f[(ktG * 4 + nw * 2 + 1) * 32 + lane];
                            float* d = D + mt * 8 + nw * 4;
                            mma16816(d, Ahi, Bh);
                            mma16816(d, Alo, Bh);
                            mma16816(d, Ahi, Bl);
                        }
                    }
                }
                // store partial D: [s][16] rows of 64B in this warp's FP region
#pragma unroll
                for (int mt = 0; mt < 2; mt++) {
#pragma unroll
                    for (int nw = 0; nw < 2; nw++) {
                        const float* d = D + mt * 8 + nw * 4;
                        const int r0 = fpW + (mt * 16 + g) * 16 + nw * 8 + 2 * t;
                        *(float2*)(sm + r0)       = make_float2(d[0], d[1]);
                        *(float2*)(sm + r0 + 128) = make_float2(d[2], d[3]);  // row g+8
                    }
                }
#pragma unroll
                for (int i = 0; i < 4; i++) {
                    dp4[i] += __shfl_xor_sync(0xffffffffu, dp4[i], 1);
                    dp4[i] += __shfl_xor_sync(0xffffffffu, dp4[i], 2);
                }
                if (t == 0) {
                    sm[WDf + warp * 32 + g]      = dp4[0];
                    sm[WDf + warp * 32 + g + 8]  = dp4[1];
                    sm[WDf + warp * 32 + g + 16] = dp4[2];
                    sm[WDf + warp * 32 + g + 24] = dp4[3];
                }
            }
            __syncthreads();

            // ======== Update: reduce 8 warp partials + RK4 ========
            {
                float f0 = sm[B3f + i0], f1 = sm[B3f + i0 + 1];
#pragma unroll
                for (int w = 0; w < 8; w++) {
                    const int base = (w < 4) ? (w * 512) : (4096 + (w - 4) * 512);
                    float2 v = *(const float2*)(sm + base + s * 16 + i0);
                    f0 += v.x; f1 += v.y;
                }
                const float wgt = (sub == 1 || sub == 2) ? 2.0f : 1.0f;
                ka = fmaf(wgt, f0, ka);
                kb = fmaf(wgt, f1, kb);
                if ((tid & 7) == 0) {
                    float dv = 0.0f;
#pragma unroll
                    for (int w = 0; w < 8; w++) dv += sm[WDf + w * 32 + s];
                    divsum = fmaf(wgt, dv, divsum);
                }
                if (sub < 3) {
                    const float c = (sub == 2) ? DT : HDT;
                    sm[Zf + s * 20 + i0]     = fmaf(c, f0, z0a);
                    sm[Zf + s * 20 + i0 + 1] = fmaf(c, f1, z0b);
                } else {
                    z0a = fmaf(DT / 6.0f, ka, z0a);
                    z0b = fmaf(DT / 6.0f, kb, z0b);
                    ka = 0.0f; kb = 0.0f;
                    sm[Zf + s * 20 + i0]     = z0a;
                    sm[Zf + s * 20 + i0 + 1] = z0b;
                }
            }
            __syncthreads();
        }
    }

    // ---- final: logpz - logp1 ----
    float ss = z0a * z0a + z0b * z0b;
    ss += __shfl_xor_sync(0xffffffffu, ss, 1);
    ss += __shfl_xor_sync(0xffffffffu, ss, 2);
    ss += __shfl_xor_sync(0xffffffffu, ss, 4);
    if ((tid & 7) == 0)
        out[gid] = -0.5f * (ss + 16.0f * LOG2PI) + (DT / 6.0f) * divsum;
}

extern "C" void kernel_launch(void* const* d_in, const int* in_sizes, int n_in,
                              void* d_out, int out_size) {
    const float* x  = (const float*)d_in[0];
    const float* W1 = (const float*)d_in[1];
    const float* b1 = (const float*)d_in[2];
    const float* W2 = (const float*)d_in[3];
    const float* b2 = (const float*)d_in[4];
    const float* W3 = (const float*)d_in[5];
    const float* b3 = (const float*)d_in[6];
    float* out = (float*)d_out;

    comp_Bf<<<dim3(16, 32), 128>>>(W1, W2, W3);

    cudaFuncSetAttribute(cnf_mma, cudaFuncAttributeMaxDynamicSharedMemorySize, SMEMSZ);
    cnf_mma<<<NBLK, THREADS, SMEMSZ>>>(x, W1, b1, b2, W3, b3, out);
}